// round 13
// baseline (speedup 1.0000x reference)
#include <cuda_runtime.h>
#include <math_constants.h>
#include <cstdint>

#define NGROUPS 4096
#define NPAIRS  2048
#define DIM     64
#define MM      128
#define PSTR    68     // fp32 stride for 64-wide tiles
#define WPS     36     // W plane stride (uint32 slots)
#define TPS     36     // t2 plane stride
#define S1PS    68     // s1row plane stride
#define SSTR    132    // sim fp32 stride
#define PTS     132    // pT combined plane stride (hi +0, lo +68)
#define PTLO    68
#define NTHREADS 1024

// ---- smem float offsets ----
#define OFF_P1   0        // 8704 (p1 fp32; S1h overlays after pack)
#define OFF_P2   8704     // 8704 (p2 fp32; S1l overlays after pack)
#define OFF_S1H  0
#define OFF_S1L  8704
#define OFF_WH   17408    // 2304 (64x36)  -> partials after T phase
#define OFF_WL   19712    // 2304
#define OFF_H1   22016    // 8704
#define OFF_H2   30720    // 8704
#define OFF_SIM  22016    // overlay over h1/h2 (16896)
#define OFF_T1   39424    // 8704 fp32 (t1) -> p1T planes after sim
#define OFF_T2H  48128    // 4608 (128x36) -> p2T planes after sim
#define OFF_T2L  52736    // 4608
#define OFF_P1T  39424    // 8448 = 64*132
#define OFF_P2T  47872    // 8448 -> 56320
#define OFF_STAT 57344    // am, bn (128 ea)
#define SMEM_BYTES (58112 * 4)   // 232448

// partials live in the dead W region after the T phase
#define OFF_RPM  17408    // rowPm [4][128]  (becomes fac after merge)
#define OFF_RPS  17920    // rowPs [4][128]
#define OFF_CPM  18432    // colPm [8][128]
#define OFF_CPS  19456    // colPs [8][128]

__device__ int g_off[NGROUPS];
__device__ int g_size[NGROUPS];

__global__ void scan_kernel(const int* __restrict__ raw) {
    __shared__ int wsum[32];
    const int stride =
        (raw[1] == 0 && raw[3] == 0 && raw[5] == 0 && raw[7] == 0) ? 2 : 1;
    int tid = threadIdx.x;
    int base = tid * 4;
    int v[4]; int s = 0;
#pragma unroll
    for (int i = 0; i < 4; i++) { v[i] = s; s += raw[(base + i) * stride]; }
    int lane = tid & 31, w = tid >> 5;
    int x = s;
#pragma unroll
    for (int d = 1; d < 32; d <<= 1) { int y = __shfl_up_sync(0xffffffffu, x, d); if (lane >= d) x += y; }
    if (lane == 31) wsum[w] = x;
    int excl = x - s;
    __syncthreads();
    if (w == 0) {
        int ws = wsum[lane]; int xx = ws;
#pragma unroll
        for (int d = 1; d < 32; d <<= 1) { int y = __shfl_up_sync(0xffffffffu, xx, d); if (lane >= d) xx += y; }
        wsum[lane] = xx - ws;
    }
    __syncthreads();
    int off = wsum[w] + excl;
#pragma unroll
    for (int i = 0; i < 4; i++) {
        g_off[base + i]  = off + v[i];
        g_size[base + i] = raw[(base + i) * stride];
    }
}

__device__ __forceinline__ void split_pair(float x0, float x1, uint32_t& h, uint32_t& l) {
    asm("cvt.rn.bf16x2.f32 %0, %1, %2;" : "=r"(h) : "f"(x1), "f"(x0));
    float h0 = __uint_as_float(h << 16);
    float h1 = __uint_as_float(h & 0xFFFF0000u);
    float l0 = x0 - h0, l1 = x1 - h1;
    asm("cvt.rn.bf16x2.f32 %0, %1, %2;" : "=r"(l) : "f"(l1), "f"(l0));
}

__device__ __forceinline__ void mma16(float* c, const uint32_t* a, const uint32_t* b) {
    asm volatile("mma.sync.aligned.m16n8k16.row.col.f32.bf16.bf16.f32 "
        "{%0,%1,%2,%3},{%4,%5,%6,%7},{%8,%9},{%0,%1,%2,%3};"
        : "+f"(c[0]), "+f"(c[1]), "+f"(c[2]), "+f"(c[3])
        : "r"(a[0]), "r"(a[1]), "r"(a[2]), "r"(a[3]), "r"(b[0]), "r"(b[1]));
}

// A fragment from fp32 row-major (stride AS), split in-flight.
__device__ __forceinline__ void load_a_rm(const float* __restrict__ A, int AS, int r0, int k0,
                                          int g, int t, uint32_t* ah, uint32_t* al) {
    const float* a0p = A + (r0 + g) * AS + k0 + 2 * t;
    const float* a1p = a0p + 8 * AS;
    float2 x0 = *(const float2*)a0p;
    float2 x1 = *(const float2*)a1p;
    float2 x2 = *(const float2*)(a0p + 8);
    float2 x3 = *(const float2*)(a1p + 8);
    split_pair(x0.x, x0.y, ah[0], al[0]);
    split_pair(x1.x, x1.y, ah[1], al[1]);
    split_pair(x2.x, x2.y, ah[2], al[2]);
    split_pair(x3.x, x3.y, ah[3], al[3]);
}

// 16x32 warp GEMM: A fp32 row-major (in-flight split), B packed hi/lo planes [n][k/2].
__device__ __forceinline__ void gemm_packedB32(
    float acc[4][4], const float* __restrict__ Afp, int AS, int r0,
    const uint32_t* __restrict__ Bh, const uint32_t* __restrict__ Bl, int BPS,
    int nbase, int ks16, int g, int t)
{
    for (int kk = 0; kk < ks16; kk++) {
        int k0 = kk << 4;
        uint32_t ah[4], al[4];
        load_a_rm(Afp, AS, r0, k0, g, t, ah, al);
        int slot = (k0 >> 1) + t;
#pragma unroll
        for (int n8 = 0; n8 < 4; n8++) {
            int nr = nbase + (n8 << 3) + g;
            uint32_t bh[2] = { Bh[nr * BPS + slot], Bh[nr * BPS + slot + 4] };
            uint32_t bl[2] = { Bl[nr * BPS + slot], Bl[nr * BPS + slot + 4] };
            mma16(acc[n8], ah, bh);
            mma16(acc[n8], al, bh);
            mma16(acc[n8], ah, bl);
        }
    }
}

__global__ __launch_bounds__(NTHREADS) void cross_kernel(
    const float* __restrict__ data, const float* __restrict__ W1g,
    const float* __restrict__ b1g, const float* __restrict__ W2g,
    const float* __restrict__ b2g,
    float* __restrict__ res_out, float* __restrict__ s1_out, float* __restrict__ s2_out)
{
    extern __shared__ float smf[];
    float* p1 = smf + OFF_P1;
    float* p2 = smf + OFF_P2;
    uint32_t* Wh = (uint32_t*)(smf + OFF_WH);
    uint32_t* Wl = (uint32_t*)(smf + OFF_WL);
    float* simb = smf + OFF_SIM;
    float* t1   = smf + OFF_T1;
    uint32_t* T2h = (uint32_t*)(smf + OFF_T2H);
    uint32_t* T2l = (uint32_t*)(smf + OFF_T2L);
    uint32_t* p1T = (uint32_t*)(smf + OFF_P1T);   // valid after merge/pack phase
    uint32_t* p2T = (uint32_t*)(smf + OFF_P2T);
    uint32_t* S1h = (uint32_t*)(smf + OFF_S1H);   // valid after materialize
    uint32_t* S1l = (uint32_t*)(smf + OFF_S1L);
    float* rowPm = smf + OFF_RPM;   // -> fac[q][m] after merge
    float* rowPs = smf + OFF_RPS;
    float* colPm = smf + OFF_CPM;
    float* colPs = smf + OFF_CPS;
    float* am     = smf + OFF_STAT;
    float* bn     = smf + OFF_STAT + 128;

    const int tid = threadIdx.x;
    const int b   = blockIdx.x;
    const int gp1 = 2 * b, gp2 = 2 * b + 1;
    const int n1 = g_size[gp1], n2 = g_size[gp2];
    const int off1 = g_off[gp1], off2 = g_off[gp2];

    const int w = tid >> 5, lane = tid & 31;
    const int g = lane >> 2, t = lane & 3;

    // ---- load: pack W1 planes; p1/p2 fp32 zero-padded ----
    for (int i = tid; i < 2048; i += NTHREADS) {
        int n = i & 63, ks = i >> 6;
        uint32_t h, l;
        split_pair(W1g[(2 * ks) * 64 + n], W1g[(2 * ks + 1) * 64 + n], h, l);
        Wh[n * WPS + ks] = h; Wl[n * WPS + ks] = l;
    }
    for (int it = tid; it < MM * 16; it += NTHREADS) {
        int r = it >> 4, c4 = (it & 15) << 2;
        float4 z = make_float4(0.f, 0.f, 0.f, 0.f);
        float4 v1 = (r < n1) ? *(const float4*)(data + (size_t)(off1 + r) * DIM + c4) : z;
        float4 v2 = (r < n2) ? *(const float4*)(data + (size_t)(off2 + r) * DIM + c4) : z;
        *(float4*)(p1 + r * PSTR + c4) = v1;
        *(float4*)(p2 + r * PSTR + c4) = v2;
    }
    __syncthreads();

    // ---- H: h = relu(p @ W1 + b1); 32 jobs = (half, m-tile, n-half32) ----
    {
        int half = w >> 4, mt = (w >> 1) & 7, nh = w & 1;
        int m0 = mt << 4, nb = nh << 5;
        int n = half ? n2 : n1;
        const float* pin = half ? p2 : p1;
        float* hout = smf + (half ? OFF_H2 : OFF_H1);
        if (m0 < n) {
            float acc[4][4];
#pragma unroll
            for (int n8 = 0; n8 < 4; n8++) {
                float2 bv = __ldg((const float2*)(b1g + nb + (n8 << 3) + 2 * t));
                acc[n8][0] = bv.x; acc[n8][1] = bv.y; acc[n8][2] = bv.x; acc[n8][3] = bv.y;
            }
            gemm_packedB32(acc, pin, PSTR, m0, Wh, Wl, WPS, nb, 4, g, t);
#pragma unroll
            for (int n8 = 0; n8 < 4; n8++) {
                int c = nb + (n8 << 3) + 2 * t;
                *(float2*)(hout + (m0 + g) * PSTR + c) =
                    make_float2(fmaxf(acc[n8][0], 0.f), fmaxf(acc[n8][1], 0.f));
                *(float2*)(hout + (m0 + g + 8) * PSTR + c) =
                    make_float2(fmaxf(acc[n8][2], 0.f), fmaxf(acc[n8][3], 0.f));
            }
        }
    }
    __syncthreads();
    // swap: pack W2 planes
    for (int i = tid; i < 2048; i += NTHREADS) {
        int n = i & 63, ks = i >> 6;
        uint32_t h, l;
        split_pair(W2g[(2 * ks) * 64 + n], W2g[(2 * ks + 1) * 64 + n], h, l);
        Wh[n * WPS + ks] = h; Wl[n * WPS + ks] = l;
    }
    __syncthreads();

    // ---- T: t = h @ W2 + b2; half0 -> t1 fp32, half1 -> t2 packed planes ----
    {
        int half = w >> 4, mt = (w >> 1) & 7, nh = w & 1;
        int m0 = mt << 4, nb = nh << 5;
        int n = half ? n2 : n1;
        const float* hin = smf + (half ? OFF_H2 : OFF_H1);
        if (m0 < n) {
            float acc[4][4];
#pragma unroll
            for (int n8 = 0; n8 < 4; n8++) {
                float2 bv = __ldg((const float2*)(b2g + nb + (n8 << 3) + 2 * t));
                acc[n8][0] = bv.x; acc[n8][1] = bv.y; acc[n8][2] = bv.x; acc[n8][3] = bv.y;
            }
            gemm_packedB32(acc, hin, PSTR, m0, Wh, Wl, WPS, nb, 4, g, t);
            if (half == 0) {
#pragma unroll
                for (int n8 = 0; n8 < 4; n8++) {
                    int c = nb + (n8 << 3) + 2 * t;
                    *(float2*)(t1 + (m0 + g) * PSTR + c) = make_float2(acc[n8][0], acc[n8][1]);
                    *(float2*)(t1 + (m0 + g + 8) * PSTR + c) = make_float2(acc[n8][2], acc[n8][3]);
                }
            } else {
#pragma unroll
                for (int n8 = 0; n8 < 4; n8++) {
                    int cs = (nb >> 1) + (n8 << 2) + t;
                    uint32_t h, l;
                    split_pair(acc[n8][0], acc[n8][1], h, l);
                    T2h[(m0 + g) * TPS + cs] = h; T2l[(m0 + g) * TPS + cs] = l;
                    split_pair(acc[n8][2], acc[n8][3], h, l);
                    T2h[(m0 + g + 8) * TPS + cs] = h; T2l[(m0 + g + 8) * TPS + cs] = l;
                }
            }
        }
    }
    __syncthreads();

    // ---- sim = t1 @ t2^T ; fused stats partials; store e = exp(v - Mw) ----
    {
        int mt = w >> 2, nq = w & 3;
        int m0 = mt << 4, nb = nq << 5;
        const bool active = (m0 < n1 && nb < n2);
        float Mw = -CUDART_INF_F;
        float rs1 = 0.f, rs2 = 0.f;
        float cs[4][2] = {{0.f,0.f},{0.f,0.f},{0.f,0.f},{0.f,0.f}};
        if (active) {
            float acc[4][4];
#pragma unroll
            for (int n8 = 0; n8 < 4; n8++) { acc[n8][0] = 0.f; acc[n8][1] = 0.f; acc[n8][2] = 0.f; acc[n8][3] = 0.f; }
            gemm_packedB32(acc, t1, PSTR, m0, T2h, T2l, TPS, nb, 4, g, t);
            const bool rv1 = (m0 + g) < n1, rv2 = (m0 + g + 8) < n1;
#pragma unroll
            for (int n8 = 0; n8 < 4; n8++) {
                int c0 = nb + (n8 << 3) + 2 * t;
                bool cv0 = c0 < n2, cv1 = (c0 + 1) < n2;
                float x0 = (rv1 && cv0) ? acc[n8][0] : -CUDART_INF_F;
                float x1 = (rv1 && cv1) ? acc[n8][1] : -CUDART_INF_F;
                float x2 = (rv2 && cv0) ? acc[n8][2] : -CUDART_INF_F;
                float x3 = (rv2 && cv1) ? acc[n8][3] : -CUDART_INF_F;
                Mw = fmaxf(Mw, fmaxf(fmaxf(x0, x1), fmaxf(x2, x3)));
            }
#pragma unroll
            for (int d = 1; d < 32; d <<= 1)
                Mw = fmaxf(Mw, __shfl_xor_sync(0xffffffffu, Mw, d));
#pragma unroll
            for (int n8 = 0; n8 < 4; n8++) {
                int c0 = nb + (n8 << 3) + 2 * t;
                bool cv0 = c0 < n2, cv1 = (c0 + 1) < n2;
                float e0 = (rv1 && cv0) ? __expf(acc[n8][0] - Mw) : 0.f;
                float e1 = (rv1 && cv1) ? __expf(acc[n8][1] - Mw) : 0.f;
                float e2 = (rv2 && cv0) ? __expf(acc[n8][2] - Mw) : 0.f;
                float e3 = (rv2 && cv1) ? __expf(acc[n8][3] - Mw) : 0.f;
                rs1 += e0 + e1;
                rs2 += e2 + e3;
                cs[n8][0] = e0 + e2;
                cs[n8][1] = e1 + e3;
                // store e-values (masked) instead of raw v
                *(float2*)(simb + (m0 + g) * SSTR + c0) = make_float2(e0, e1);
                *(float2*)(simb + (m0 + g + 8) * SSTR + c0) = make_float2(e2, e3);
            }
        }
        rs1 += __shfl_xor_sync(0xffffffffu, rs1, 1);
        rs1 += __shfl_xor_sync(0xffffffffu, rs1, 2);
        rs2 += __shfl_xor_sync(0xffffffffu, rs2, 1);
        rs2 += __shfl_xor_sync(0xffffffffu, rs2, 2);
#pragma unroll
        for (int n8 = 0; n8 < 4; n8++) {
#pragma unroll
            for (int j = 0; j < 2; j++) {
                cs[n8][j] += __shfl_xor_sync(0xffffffffu, cs[n8][j], 4);
                cs[n8][j] += __shfl_xor_sync(0xffffffffu, cs[n8][j], 8);
                cs[n8][j] += __shfl_xor_sync(0xffffffffu, cs[n8][j], 16);
            }
        }
        if (t == 0) {
            rowPm[nq * 128 + m0 + g] = Mw;      rowPs[nq * 128 + m0 + g] = rs1;
            rowPm[nq * 128 + m0 + g + 8] = Mw;  rowPs[nq * 128 + m0 + g + 8] = rs2;
        }
        if (g == 0) {
#pragma unroll
            for (int n8 = 0; n8 < 4; n8++) {
                int c0 = nb + (n8 << 3) + 2 * t;
                colPm[mt * 128 + c0] = Mw;     colPs[mt * 128 + c0] = cs[n8][0];
                colPm[mt * 128 + c0 + 1] = Mw; colPs[mt * 128 + c0 + 1] = cs[n8][1];
            }
        }
    }
    __syncthreads();

    // ---- merge (tiny) + pack pT planes into dead t-region ----
    if (tid < 128) {
        int r = tid;
        float M = -CUDART_INF_F;
#pragma unroll
        for (int q = 0; q < 4; q++) M = fmaxf(M, rowPm[q * 128 + r]);
        if (r < n1) {
            float ex[4]; float S = 0.f;
#pragma unroll
            for (int q = 0; q < 4; q++) {
                ex[q] = __expf(rowPm[q * 128 + r] - M);
                S += rowPs[q * 128 + r] * ex[q];
            }
            float ri = 1.f / S;
#pragma unroll
            for (int q = 0; q < 4; q++) rowPm[q * 128 + r] = ex[q] * ri;  // fac
            am[r] = __expf(M) * S;
        } else {
            am[r] = 0.f;
#pragma unroll
            for (int q = 0; q < 4; q++) rowPm[q * 128 + r] = 0.f;
        }
    } else if (tid < 256) {
        int c = tid - 128;
        float M = -CUDART_INF_F;
#pragma unroll
        for (int q = 0; q < 8; q++) M = fmaxf(M, colPm[q * 128 + c]);
        if (c < n2) {
            float S = 0.f;
#pragma unroll
            for (int q = 0; q < 8; q++)
                S += colPs[q * 128 + c] * __expf(colPm[q * 128 + c] - M);
            bn[c] = __expf(-M) / S;
        } else bn[c] = 0.f;
    }
    // pT pack: pT[d][s] = bf16 planes of (p[2s][d], p[2s+1][d]); reads p fp32, writes dead t-region
    for (int i = tid; i < 8192; i += NTHREADS) {
        int s_lo = i & 7, d_lo = (i >> 3) & 3;
        int blk = i >> 5;
        int d = ((blk & 15) << 2) + d_lo;
        int s = (((blk >> 4) & 7) << 3) + s_lo;
        int tn = i >> 12;
        const float* P = tn ? p2 : p1;
        uint32_t* pT = tn ? p2T : p1T;
        float a0 = P[(2 * s) * PSTR + d];
        float a1 = P[(2 * s + 1) * PSTR + d];
        uint32_t h, l;
        split_pair(a0, a1, h, l);
        pT[d * PTS + s] = h;
        pT[d * PTS + PTLO + s] = l;
    }
    __syncthreads();

    // ---- materialize: s1 = e*fac, s2 = s1*am*bn ; gmem + simb(s1) + S1 planes (over p) ----
    {
        const float inv1 = 1.f / (float)(MM - n1);
        const float inv2 = 1.f / (float)(MM - n2);
        for (int it = tid; it < MM * 32; it += NTHREADS) {
            int m = it >> 5, n0 = (it & 31) << 2;
            int nq = n0 >> 5;
            float4 a, c;
            if (m < n1) {
                float4 e4 = *(const float4*)(simb + m * SSTR + n0);
                float fac = rowPm[nq * 128 + m];
                float amm = am[m];
                float4 bn4 = *(const float4*)(bn + n0);
                a.x = (n0 + 0 < n2) ? e4.x * fac : 0.f;
                a.y = (n0 + 1 < n2) ? e4.y * fac : 0.f;
                a.z = (n0 + 2 < n2) ? e4.z * fac : 0.f;
                a.w = (n0 + 3 < n2) ? e4.w * fac : 0.f;
                c.x = a.x * amm * bn4.x;
                c.y = a.y * amm * bn4.y;
                c.z = a.z * amm * bn4.z;
                c.w = a.w * amm * bn4.w;
            } else {
                a.x = (n0 + 0 < n2) ? 0.f : inv2;
                a.y = (n0 + 1 < n2) ? 0.f : inv2;
                a.z = (n0 + 2 < n2) ? 0.f : inv2;
                a.w = (n0 + 3 < n2) ? 0.f : inv2;
                c.x = (n0 + 0 < n2) ? 0.f : inv1;
                c.y = (n0 + 1 < n2) ? 0.f : inv1;
                c.z = (n0 + 2 < n2) ? 0.f : inv1;
                c.w = (n0 + 3 < n2) ? 0.f : inv1;
            }
            size_t go = (size_t)b * (MM * MM) + (size_t)m * MM + n0;
            *(float4*)(s1_out + go) = a;
            *(float4*)(s2_out + go) = c;
            *(float4*)(simb + m * SSTR + n0) = a;        // s1 fp32 for cn
            uint32_t h0, l0, h1, l1;
            split_pair(a.x, a.y, h0, l0);
            split_pair(a.z, a.w, h1, l1);
            int s = n0 >> 1;
            *(uint2*)(S1h + m * S1PS + s) = make_uint2(h0, h1);
            *(uint2*)(S1l + m * S1PS + s) = make_uint2(l0, l1);
        }
    }
    __syncthreads();

    // ---- attention: 32 jobs (16 qn, 16 cn), B fully packed pT planes ----
    if (w < 16) {
        // qn = s1 @ p2 : A = packed S1 planes, B = p2T planes
        int mt = w >> 1, nh = w & 1;
        int m0 = mt << 4, db = nh << 5;
        if (m0 < n1) {
            float acc[4][4];
#pragma unroll
            for (int n8 = 0; n8 < 4; n8++) { acc[n8][0] = 0.f; acc[n8][1] = 0.f; acc[n8][2] = 0.f; acc[n8][3] = 0.f; }
            int ks16 = (n2 + 15) >> 4;
            for (int kk = 0; kk < ks16; kk++) {
                int slot0 = (kk << 3) + t;
                int as = (m0 + g) * S1PS + slot0;
                int as8 = as + 8 * S1PS;
                uint32_t ah[4] = { S1h[as], S1h[as8], S1h[as + 4], S1h[as8 + 4] };
                uint32_t al[4] = { S1l[as], S1l[as8], S1l[as + 4], S1l[as8 + 4] };
#pragma unroll
                for (int n8 = 0; n8 < 4; n8++) {
                    const uint32_t* bp = p2T + (db + (n8 << 3) + g) * PTS + slot0;
                    uint32_t bh[2] = { bp[0], bp[4] };
                    uint32_t bl[2] = { bp[PTLO], bp[PTLO + 4] };
                    mma16(acc[n8], ah, bh);
                    mma16(acc[n8], al, bh);
                    mma16(acc[n8], ah, bl);
                }
            }
            int m1 = m0 + g, m2 = m0 + g + 8;
#pragma unroll
            for (int n8 = 0; n8 < 4; n8++) {
                int c = db + (n8 << 3) + 2 * t;
                if (m1 < n1)
                    *(float2*)(res_out + (size_t)(off1 + m1) * DIM + c) = make_float2(acc[n8][0], acc[n8][1]);
                if (m2 < n1)
                    *(float2*)(res_out + (size_t)(off1 + m2) * DIM + c) = make_float2(acc[n8][2], acc[n8][3]);
            }
        }
    } else {
        // cn = (s1*am)^T @ p1 * bn : A = simb fp32 cols (in-flight, am-scaled), B = p1T planes
        int nt = (w - 16) >> 1, nh = w & 1;
        int nn0 = nt << 4, db = nh << 5;
        if (nn0 < n2) {
            float acc[4][4];
#pragma unroll
            for (int n8 = 0; n8 < 4; n8++) { acc[n8][0] = 0.f; acc[n8][1] = 0.f; acc[n8][2] = 0.f; acc[n8][3] = 0.f; }
            int ks16 = (n1 + 15) >> 4;
            for (int kk = 0; kk < ks16; kk++) {
                int kr = (kk << 4) + 2 * t;
                float am0 = am[kr], am1 = am[kr + 1], am2 = am[kr + 8], am3 = am[kr + 9];
                const float* s0 = simb + kr * SSTR + nn0 + g;
                const float* s8 = s0 + 8 * SSTR;
                uint32_t ah[4], al[4];
                split_pair(s0[0] * am0, s0[SSTR] * am1, ah[0], al[0]);
                split_pair(s0[8] * am0, s0[SSTR + 8] * am1, ah[1], al[1]);
                split_pair(s8[0] * am2, s8[SSTR] * am3, ah[2], al[2]);
                split_pair(s8[8] * am2, s8[SSTR + 8] * am3, ah[3], al[3]);
                int slot0 = (kk << 3) + t;
#pragma unroll
                for (int n8 = 0; n8 < 4; n8++) {
                    const uint32_t* bp = p1T + (db + (n8 << 3) + g) * PTS + slot0;
                    uint32_t bh[2] = { bp[0], bp[4] };
                    uint32_t bl[2] = { bp[PTLO], bp[PTLO + 4] };
                    mma16(acc[n8], ah, bh);
                    mma16(acc[n8], al, bh);
                    mma16(acc[n8], ah, bl);
                }
            }
            int r1 = nn0 + g, r2 = nn0 + g + 8;
            float f1 = bn[r1], f2 = bn[r2];
#pragma unroll
            for (int n8 = 0; n8 < 4; n8++) {
                int c = db + (n8 << 3) + 2 * t;
                if (r1 < n2)
                    *(float2*)(res_out + (size_t)(off2 + r1) * DIM + c) =
                        make_float2(acc[n8][0] * f1, acc[n8][1] * f1);
                if (r2 < n2)
                    *(float2*)(res_out + (size_t)(off2 + r2) * DIM + c) =
                        make_float2(acc[n8][2] * f2, acc[n8][3] * f2);
            }
        }
    }
}

extern "C" void kernel_launch(void* const* d_in, const int* in_sizes, int n_in,
                              void* d_out, int out_size) {
    const float* data = (const float*)d_in[0];
    const float* W1   = (const float*)d_in[1];
    const float* b1   = (const float*)d_in[2];
    const float* W2   = (const float*)d_in[3];
    const float* b2   = (const float*)d_in[4];
    const int*   sizes_raw = (const int*)d_in[5];

    float* out = (float*)d_out;
    size_t total_e = (size_t)in_sizes[0];        // total * DIM
    float* s1o = out + total_e;
    float* s2o = s1o + (size_t)NPAIRS * MM * MM;

    cudaFuncSetAttribute(cross_kernel, cudaFuncAttributeMaxDynamicSharedMemorySize, SMEM_BYTES);

    scan_kernel<<<1, 1024>>>(sizes_raw);
    cross_kernel<<<NPAIRS, NTHREADS, SMEM_BYTES>>>(data, W1, b1, W2, b2, out, s1o, s2o);
}

// round 14
// speedup vs baseline: 1.0412x; 1.0412x over previous
#include <cuda_runtime.h>
#include <math_constants.h>
#include <cstdint>

#define NGROUPS 4096
#define NPAIRS  2048
#define DIM     64
#define MM      128
#define PSTR    68     // fp32 stride for 64-wide tiles
#define WPS     36     // W plane stride (uint32 slots)
#define TPS     36     // t2 plane stride
#define S1PS    68     // s1row plane stride
#define SSTR    132    // sim fp32 stride
#define NTHREADS 1024

// ---- smem float offsets (R12 layout) ----
#define OFF_P1   0        // 8704
#define OFF_P2   8704     // 8704
#define OFF_WH   17408    // 2304 (64x36)  -> partials after T phase
#define OFF_WL   19712    // 2304
#define OFF_H1   22016    // 8704
#define OFF_H2   30720    // 8704
#define OFF_SIM  22016    // overlay over h1/h2 (16896)
#define OFF_T1   39424    // 8704 fp32
#define OFF_T2H  48128    // 4608 (128x36)
#define OFF_T2L  52736    // 4608
#define OFF_S1H  39424    // overlay over t1 (8704)
#define OFF_S1L  48128    // overlay over t2 planes (8704)
#define OFF_STAT 57344    // am, bn (128 ea)
#define SMEM_BYTES (58112 * 4)   // 232448

// partials live in the dead W region after the T phase
#define OFF_RPM  17408    // rowPm [4][128]  (becomes fac after merge)
#define OFF_RPS  17920    // rowPs [4][128]
#define OFF_CPM  18432    // colPm [8][128]
#define OFF_CPS  19456    // colPs [8][128]

__device__ int g_off[NGROUPS];
__device__ int g_size[NGROUPS];

__global__ void scan_kernel(const int* __restrict__ raw) {
    __shared__ int wsum[32];
    const int stride =
        (raw[1] == 0 && raw[3] == 0 && raw[5] == 0 && raw[7] == 0) ? 2 : 1;
    int tid = threadIdx.x;
    int base = tid * 4;
    int v[4]; int s = 0;
#pragma unroll
    for (int i = 0; i < 4; i++) { v[i] = s; s += raw[(base + i) * stride]; }
    int lane = tid & 31, w = tid >> 5;
    int x = s;
#pragma unroll
    for (int d = 1; d < 32; d <<= 1) { int y = __shfl_up_sync(0xffffffffu, x, d); if (lane >= d) x += y; }
    if (lane == 31) wsum[w] = x;
    int excl = x - s;
    __syncthreads();
    if (w == 0) {
        int ws = wsum[lane]; int xx = ws;
#pragma unroll
        for (int d = 1; d < 32; d <<= 1) { int y = __shfl_up_sync(0xffffffffu, xx, d); if (lane >= d) xx += y; }
        wsum[lane] = xx - ws;
    }
    __syncthreads();
    int off = wsum[w] + excl;
#pragma unroll
    for (int i = 0; i < 4; i++) {
        g_off[base + i]  = off + v[i];
        g_size[base + i] = raw[(base + i) * stride];
    }
}

__device__ __forceinline__ void split_pair(float x0, float x1, uint32_t& h, uint32_t& l) {
    asm("cvt.rn.bf16x2.f32 %0, %1, %2;" : "=r"(h) : "f"(x1), "f"(x0));
    float h0 = __uint_as_float(h << 16);
    float h1 = __uint_as_float(h & 0xFFFF0000u);
    float l0 = x0 - h0, l1 = x1 - h1;
    asm("cvt.rn.bf16x2.f32 %0, %1, %2;" : "=r"(l) : "f"(l1), "f"(l0));
}

__device__ __forceinline__ void mma16(float* c, const uint32_t* a, const uint32_t* b) {
    asm volatile("mma.sync.aligned.m16n8k16.row.col.f32.bf16.bf16.f32 "
        "{%0,%1,%2,%3},{%4,%5,%6,%7},{%8,%9},{%0,%1,%2,%3};"
        : "+f"(c[0]), "+f"(c[1]), "+f"(c[2]), "+f"(c[3])
        : "r"(a[0]), "r"(a[1]), "r"(a[2]), "r"(a[3]), "r"(b[0]), "r"(b[1]));
}

// A fragment from fp32 row-major (stride AS), split in-flight.
__device__ __forceinline__ void load_a_rm(const float* __restrict__ A, int AS, int r0, int k0,
                                          int g, int t, uint32_t* ah, uint32_t* al) {
    const float* a0p = A + (r0 + g) * AS + k0 + 2 * t;
    const float* a1p = a0p + 8 * AS;
    float2 x0 = *(const float2*)a0p;
    float2 x1 = *(const float2*)a1p;
    float2 x2 = *(const float2*)(a0p + 8);
    float2 x3 = *(const float2*)(a1p + 8);
    split_pair(x0.x, x0.y, ah[0], al[0]);
    split_pair(x1.x, x1.y, ah[1], al[1]);
    split_pair(x2.x, x2.y, ah[2], al[2]);
    split_pair(x3.x, x3.y, ah[3], al[3]);
}

// 16x32 warp GEMM: A fp32 row-major (in-flight split), B packed hi/lo planes [n][k/2].
__device__ __forceinline__ void gemm_packedB32(
    float acc[4][4], const float* __restrict__ Afp, int AS, int r0,
    const uint32_t* __restrict__ Bh, const uint32_t* __restrict__ Bl, int BPS,
    int nbase, int ks16, int g, int t)
{
    for (int kk = 0; kk < ks16; kk++) {
        int k0 = kk << 4;
        uint32_t ah[4], al[4];
        load_a_rm(Afp, AS, r0, k0, g, t, ah, al);
        int slot = (k0 >> 1) + t;
#pragma unroll
        for (int n8 = 0; n8 < 4; n8++) {
            int nr = nbase + (n8 << 3) + g;
            uint32_t bh[2] = { Bh[nr * BPS + slot], Bh[nr * BPS + slot + 4] };
            uint32_t bl[2] = { Bl[nr * BPS + slot], Bl[nr * BPS + slot + 4] };
            mma16(acc[n8], ah, bh);
            mma16(acc[n8], al, bh);
            mma16(acc[n8], ah, bl);
        }
    }
}

__global__ __launch_bounds__(NTHREADS) void cross_kernel(
    const float* __restrict__ data, const float* __restrict__ W1g,
    const float* __restrict__ b1g, const float* __restrict__ W2g,
    const float* __restrict__ b2g,
    float* __restrict__ res_out, float* __restrict__ s1_out, float* __restrict__ s2_out)
{
    extern __shared__ float smf[];
    float* p1 = smf + OFF_P1;
    float* p2 = smf + OFF_P2;
    uint32_t* Wh = (uint32_t*)(smf + OFF_WH);
    uint32_t* Wl = (uint32_t*)(smf + OFF_WL);
    float* simb = smf + OFF_SIM;
    float* t1   = smf + OFF_T1;
    uint32_t* T2h = (uint32_t*)(smf + OFF_T2H);
    uint32_t* T2l = (uint32_t*)(smf + OFF_T2L);
    uint32_t* S1h = (uint32_t*)(smf + OFF_S1H);
    uint32_t* S1l = (uint32_t*)(smf + OFF_S1L);
    float* rowPm = smf + OFF_RPM;   // -> fac[q][m] after merge
    float* rowPs = smf + OFF_RPS;
    float* colPm = smf + OFF_CPM;
    float* colPs = smf + OFF_CPS;
    float* am     = smf + OFF_STAT;
    float* bn     = smf + OFF_STAT + 128;

    const int tid = threadIdx.x;
    const int b   = blockIdx.x;
    const int gp1 = 2 * b, gp2 = 2 * b + 1;
    const int n1 = g_size[gp1], n2 = g_size[gp2];
    const int off1 = g_off[gp1], off2 = g_off[gp2];

    const int w = tid >> 5, lane = tid & 31;
    const int g = lane >> 2, t = lane & 3;

    // ---- load: pack W1 planes; p1/p2 fp32 zero-padded ----
    for (int i = tid; i < 2048; i += NTHREADS) {
        int n = i & 63, ks = i >> 6;
        uint32_t h, l;
        split_pair(W1g[(2 * ks) * 64 + n], W1g[(2 * ks + 1) * 64 + n], h, l);
        Wh[n * WPS + ks] = h; Wl[n * WPS + ks] = l;
    }
    for (int it = tid; it < MM * 16; it += NTHREADS) {
        int r = it >> 4, c4 = (it & 15) << 2;
        float4 z = make_float4(0.f, 0.f, 0.f, 0.f);
        float4 v1 = (r < n1) ? *(const float4*)(data + (size_t)(off1 + r) * DIM + c4) : z;
        float4 v2 = (r < n2) ? *(const float4*)(data + (size_t)(off2 + r) * DIM + c4) : z;
        *(float4*)(p1 + r * PSTR + c4) = v1;
        *(float4*)(p2 + r * PSTR + c4) = v2;
    }
    __syncthreads();

    // ---- H: h = relu(p @ W1 + b1); 32 jobs = (half, m-tile, n-half32) ----
    {
        int half = w >> 4, mt = (w >> 1) & 7, nh = w & 1;
        int m0 = mt << 4, nb = nh << 5;
        int n = half ? n2 : n1;
        const float* pin = half ? p2 : p1;
        float* hout = smf + (half ? OFF_H2 : OFF_H1);
        if (m0 < n) {
            float acc[4][4];
#pragma unroll
            for (int n8 = 0; n8 < 4; n8++) {
                float2 bv = __ldg((const float2*)(b1g + nb + (n8 << 3) + 2 * t));
                acc[n8][0] = bv.x; acc[n8][1] = bv.y; acc[n8][2] = bv.x; acc[n8][3] = bv.y;
            }
            gemm_packedB32(acc, pin, PSTR, m0, Wh, Wl, WPS, nb, 4, g, t);
#pragma unroll
            for (int n8 = 0; n8 < 4; n8++) {
                int c = nb + (n8 << 3) + 2 * t;
                *(float2*)(hout + (m0 + g) * PSTR + c) =
                    make_float2(fmaxf(acc[n8][0], 0.f), fmaxf(acc[n8][1], 0.f));
                *(float2*)(hout + (m0 + g + 8) * PSTR + c) =
                    make_float2(fmaxf(acc[n8][2], 0.f), fmaxf(acc[n8][3], 0.f));
            }
        }
    }
    __syncthreads();
    // swap: pack W2 planes
    for (int i = tid; i < 2048; i += NTHREADS) {
        int n = i & 63, ks = i >> 6;
        uint32_t h, l;
        split_pair(W2g[(2 * ks) * 64 + n], W2g[(2 * ks + 1) * 64 + n], h, l);
        Wh[n * WPS + ks] = h; Wl[n * WPS + ks] = l;
    }
    __syncthreads();

    // ---- T: t = h @ W2 + b2; half0 -> t1 fp32, half1 -> t2 packed planes ----
    {
        int half = w >> 4, mt = (w >> 1) & 7, nh = w & 1;
        int m0 = mt << 4, nb = nh << 5;
        int n = half ? n2 : n1;
        const float* hin = smf + (half ? OFF_H2 : OFF_H1);
        if (m0 < n) {
            float acc[4][4];
#pragma unroll
            for (int n8 = 0; n8 < 4; n8++) {
                float2 bv = __ldg((const float2*)(b2g + nb + (n8 << 3) + 2 * t));
                acc[n8][0] = bv.x; acc[n8][1] = bv.y; acc[n8][2] = bv.x; acc[n8][3] = bv.y;
            }
            gemm_packedB32(acc, hin, PSTR, m0, Wh, Wl, WPS, nb, 4, g, t);
            if (half == 0) {
#pragma unroll
                for (int n8 = 0; n8 < 4; n8++) {
                    int c = nb + (n8 << 3) + 2 * t;
                    *(float2*)(t1 + (m0 + g) * PSTR + c) = make_float2(acc[n8][0], acc[n8][1]);
                    *(float2*)(t1 + (m0 + g + 8) * PSTR + c) = make_float2(acc[n8][2], acc[n8][3]);
                }
            } else {
#pragma unroll
                for (int n8 = 0; n8 < 4; n8++) {
                    int cs = (nb >> 1) + (n8 << 2) + t;
                    uint32_t h, l;
                    split_pair(acc[n8][0], acc[n8][1], h, l);
                    T2h[(m0 + g) * TPS + cs] = h; T2l[(m0 + g) * TPS + cs] = l;
                    split_pair(acc[n8][2], acc[n8][3], h, l);
                    T2h[(m0 + g + 8) * TPS + cs] = h; T2l[(m0 + g + 8) * TPS + cs] = l;
                }
            }
        }
    }
    __syncthreads();

    // ---- sim = t1 @ t2^T ; fused stats partials; store e = exp(v - Mw) ----
    {
        int mt = w >> 2, nq = w & 3;
        int m0 = mt << 4, nb = nq << 5;
        const bool active = (m0 < n1 && nb < n2);
        float Mw = -CUDART_INF_F;
        float rs1 = 0.f, rs2 = 0.f;
        float cs[4][2] = {{0.f,0.f},{0.f,0.f},{0.f,0.f},{0.f,0.f}};
        if (active) {
            float acc[4][4];
#pragma unroll
            for (int n8 = 0; n8 < 4; n8++) { acc[n8][0] = 0.f; acc[n8][1] = 0.f; acc[n8][2] = 0.f; acc[n8][3] = 0.f; }
            gemm_packedB32(acc, t1, PSTR, m0, T2h, T2l, TPS, nb, 4, g, t);
            const bool rv1 = (m0 + g) < n1, rv2 = (m0 + g + 8) < n1;
#pragma unroll
            for (int n8 = 0; n8 < 4; n8++) {
                int c0 = nb + (n8 << 3) + 2 * t;
                bool cv0 = c0 < n2, cv1 = (c0 + 1) < n2;
                float x0 = (rv1 && cv0) ? acc[n8][0] : -CUDART_INF_F;
                float x1 = (rv1 && cv1) ? acc[n8][1] : -CUDART_INF_F;
                float x2 = (rv2 && cv0) ? acc[n8][2] : -CUDART_INF_F;
                float x3 = (rv2 && cv1) ? acc[n8][3] : -CUDART_INF_F;
                Mw = fmaxf(Mw, fmaxf(fmaxf(x0, x1), fmaxf(x2, x3)));
            }
#pragma unroll
            for (int d = 1; d < 32; d <<= 1)
                Mw = fmaxf(Mw, __shfl_xor_sync(0xffffffffu, Mw, d));
#pragma unroll
            for (int n8 = 0; n8 < 4; n8++) {
                int c0 = nb + (n8 << 3) + 2 * t;
                bool cv0 = c0 < n2, cv1 = (c0 + 1) < n2;
                float e0 = (rv1 && cv0) ? __expf(acc[n8][0] - Mw) : 0.f;
                float e1 = (rv1 && cv1) ? __expf(acc[n8][1] - Mw) : 0.f;
                float e2 = (rv2 && cv0) ? __expf(acc[n8][2] - Mw) : 0.f;
                float e3 = (rv2 && cv1) ? __expf(acc[n8][3] - Mw) : 0.f;
                rs1 += e0 + e1;
                rs2 += e2 + e3;
                cs[n8][0] = e0 + e2;
                cs[n8][1] = e1 + e3;
                // store masked e-values instead of raw v
                *(float2*)(simb + (m0 + g) * SSTR + c0) = make_float2(e0, e1);
                *(float2*)(simb + (m0 + g + 8) * SSTR + c0) = make_float2(e2, e3);
            }
        }
        rs1 += __shfl_xor_sync(0xffffffffu, rs1, 1);
        rs1 += __shfl_xor_sync(0xffffffffu, rs1, 2);
        rs2 += __shfl_xor_sync(0xffffffffu, rs2, 1);
        rs2 += __shfl_xor_sync(0xffffffffu, rs2, 2);
#pragma unroll
        for (int n8 = 0; n8 < 4; n8++) {
#pragma unroll
            for (int j = 0; j < 2; j++) {
                cs[n8][j] += __shfl_xor_sync(0xffffffffu, cs[n8][j], 4);
                cs[n8][j] += __shfl_xor_sync(0xffffffffu, cs[n8][j], 8);
                cs[n8][j] += __shfl_xor_sync(0xffffffffu, cs[n8][j], 16);
            }
        }
        if (t == 0) {
            rowPm[nq * 128 + m0 + g] = Mw;      rowPs[nq * 128 + m0 + g] = rs1;
            rowPm[nq * 128 + m0 + g + 8] = Mw;  rowPs[nq * 128 + m0 + g + 8] = rs2;
        }
        if (g == 0) {
#pragma unroll
            for (int n8 = 0; n8 < 4; n8++) {
                int c0 = nb + (n8 << 3) + 2 * t;
                colPm[mt * 128 + c0] = Mw;     colPs[mt * 128 + c0] = cs[n8][0];
                colPm[mt * 128 + c0 + 1] = Mw; colPs[mt * 128 + c0 + 1] = cs[n8][1];
            }
        }
    }
    __syncthreads();

    // ---- stats merge (tiny): rowPm -> fac, am, bn ----
    if (tid < 128) {
        int r = tid;
        float M = -CUDART_INF_F;
#pragma unroll
        for (int q = 0; q < 4; q++) M = fmaxf(M, rowPm[q * 128 + r]);
        if (r < n1) {
            float ex[4]; float S = 0.f;
#pragma unroll
            for (int q = 0; q < 4; q++) {
                ex[q] = __expf(rowPm[q * 128 + r] - M);
                S += rowPs[q * 128 + r] * ex[q];
            }
            float ri = 1.f / S;
#pragma unroll
            for (int q = 0; q < 4; q++) rowPm[q * 128 + r] = ex[q] * ri;  // fac
            am[r] = __expf(M) * S;
        } else {
            am[r] = 0.f;
#pragma unroll
            for (int q = 0; q < 4; q++) rowPm[q * 128 + r] = 0.f;
        }
    } else if (tid < 256) {
        int c = tid - 128;
        float M = -CUDART_INF_F;
#pragma unroll
        for (int q = 0; q < 8; q++) M = fmaxf(M, colPm[q * 128 + c]);
        if (c < n2) {
            float S = 0.f;
#pragma unroll
            for (int q = 0; q < 8; q++)
                S += colPs[q * 128 + c] * __expf(colPm[q * 128 + c] - M);
            bn[c] = __expf(-M) / S;
        } else bn[c] = 0.f;
    }
    __syncthreads();

    // ---- materialize: s1 = e*fac, s2 = s1*am*bn ; gmem + simb(s1) + S1 planes ----
    {
        const float inv1 = 1.f / (float)(MM - n1);
        const float inv2 = 1.f / (float)(MM - n2);
        for (int it = tid; it < MM * 32; it += NTHREADS) {
            int m = it >> 5, n0 = (it & 31) << 2;
            int nq = n0 >> 5;
            float4 a, c;
            if (m < n1) {
                float4 e4 = *(const float4*)(simb + m * SSTR + n0);
                float fac = rowPm[nq * 128 + m];
                float amm = am[m];
                float4 bn4 = *(const float4*)(bn + n0);
                a.x = e4.x * fac;
                a.y = e4.y * fac;
                a.z = e4.z * fac;
                a.w = e4.w * fac;
                c.x = a.x * amm * bn4.x;
                c.y = a.y * amm * bn4.y;
                c.z = a.z * amm * bn4.z;
                c.w = a.w * amm * bn4.w;
            } else {
                a.x = (n0 + 0 < n2) ? 0.f : inv2;
                a.y = (n0 + 1 < n2) ? 0.f : inv2;
                a.z = (n0 + 2 < n2) ? 0.f : inv2;
                a.w = (n0 + 3 < n2) ? 0.f : inv2;
                c.x = (n0 + 0 < n2) ? 0.f : inv1;
                c.y = (n0 + 1 < n2) ? 0.f : inv1;
                c.z = (n0 + 2 < n2) ? 0.f : inv1;
                c.w = (n0 + 3 < n2) ? 0.f : inv1;
            }
            size_t go = (size_t)b * (MM * MM) + (size_t)m * MM + n0;
            *(float4*)(s1_out + go) = a;
            *(float4*)(s2_out + go) = c;
            *(float4*)(simb + m * SSTR + n0) = a;
            uint32_t h0, l0, h1, l1;
            split_pair(a.x, a.y, h0, l0);
            split_pair(a.z, a.w, h1, l1);
            int s = n0 >> 1;
            *(uint2*)(S1h + m * S1PS + s) = make_uint2(h0, h1);
            *(uint2*)(S1l + m * S1PS + s) = make_uint2(l0, l1);
        }
    }
    __syncthreads();

    // ---- attention: 32 jobs (16 qn, 16 cn), each 16 rows x 32 cols ----
    if (w < 16) {
        // qn = s1 @ p2 : A = packed S1 planes, B = fp32 p2 (in-flight split)
        int mt = w >> 1, nh = w & 1;
        int m0 = mt << 4, db = nh << 5;
        if (m0 < n1) {
            float acc[4][4];
#pragma unroll
            for (int n8 = 0; n8 < 4; n8++) { acc[n8][0] = 0.f; acc[n8][1] = 0.f; acc[n8][2] = 0.f; acc[n8][3] = 0.f; }
            int ks16 = (n2 + 15) >> 4;
            for (int kk = 0; kk < ks16; kk++) {
                int k0 = kk << 4;
                int as = (m0 + g) * S1PS + (k0 >> 1) + t;
                int as8 = as + 8 * S1PS;
                uint32_t ah[4] = { S1h[as], S1h[as8], S1h[as + 4], S1h[as8 + 4] };
                uint32_t al[4] = { S1l[as], S1l[as8], S1l[as + 4], S1l[as8 + 4] };
#pragma unroll
                for (int n8 = 0; n8 < 4; n8++) {
                    int nc = db + (n8 << 3) + g;
                    const float* bp = p2 + (k0 + 2 * t) * PSTR + nc;
                    uint32_t bh[2], bl[2];
                    split_pair(bp[0], bp[PSTR], bh[0], bl[0]);
                    split_pair(bp[8 * PSTR], bp[9 * PSTR], bh[1], bl[1]);
                    mma16(acc[n8], ah, bh);
                    mma16(acc[n8], al, bh);
                    mma16(acc[n8], ah, bl);
                }
            }
            int m1 = m0 + g, m2 = m0 + g + 8;
#pragma unroll
            for (int n8 = 0; n8 < 4; n8++) {
                int c = db + (n8 << 3) + 2 * t;
                if (m1 < n1)
                    *(float2*)(res_out + (size_t)(off1 + m1) * DIM + c) = make_float2(acc[n8][0], acc[n8][1]);
                if (m2 < n1)
                    *(float2*)(res_out + (size_t)(off1 + m2) * DIM + c) = make_float2(acc[n8][2], acc[n8][3]);
            }
        }
    } else {
        // cn = (s1*am)^T @ p1 * bn : A = simb fp32 cols (in-flight, am-scaled), B = fp32 p1
        int nt = (w - 16) >> 1, nh = w & 1;
        int nn0 = nt << 4, db = nh << 5;
        if (nn0 < n2) {
            float acc[4][4];
#pragma unroll
            for (int n8 = 0; n8 < 4; n8++) { acc[n8][0] = 0.f; acc[n8][1] = 0.f; acc[n8][2] = 0.f; acc[n8][3] = 0.f; }
            int ks16 = (n1 + 15) >> 4;
            for (int kk = 0; kk < ks16; kk++) {
                int kr = (kk << 4) + 2 * t;
                float am0 = am[kr], am1 = am[kr + 1], am2 = am[kr + 8], am3 = am[kr + 9];
                const float* s0 = simb + kr * SSTR + nn0 + g;
                const float* s8 = s0 + 8 * SSTR;
                uint32_t ah[4], al[4];
                split_pair(s0[0] * am0, s0[SSTR] * am1, ah[0], al[0]);
                split_pair(s0[8] * am0, s0[SSTR + 8] * am1, ah[1], al[1]);
                split_pair(s8[0] * am2, s8[SSTR] * am3, ah[2], al[2]);
                split_pair(s8[8] * am2, s8[SSTR + 8] * am3, ah[3], al[3]);
#pragma unroll
                for (int n8 = 0; n8 < 4; n8++) {
                    int nc = db + (n8 << 3) + g;
                    const float* bp = p1 + ((kk << 4) + 2 * t) * PSTR + nc;
                    uint32_t bh[2], bl[2];
                    split_pair(bp[0], bp[PSTR], bh[0], bl[0]);
                    split_pair(bp[8 * PSTR], bp[9 * PSTR], bh[1], bl[1]);
                    mma16(acc[n8], ah, bh);
                    mma16(acc[n8], al, bh);
                    mma16(acc[n8], ah, bl);
                }
            }
            int r1 = nn0 + g, r2 = nn0 + g + 8;
            float f1 = bn[r1], f2 = bn[r2];
#pragma unroll
            for (int n8 = 0; n8 < 4; n8++) {
                int c = db + (n8 << 3) + 2 * t;
                if (r1 < n2)
                    *(float2*)(res_out + (size_t)(off2 + r1) * DIM + c) =
                        make_float2(acc[n8][0] * f1, acc[n8][1] * f1);
                if (r2 < n2)
                    *(float2*)(res_out + (size_t)(off2 + r2) * DIM + c) =
                        make_float2(acc[n8][2] * f2, acc[n8][3] * f2);
            }
        }
    }
}

extern "C" void kernel_launch(void* const* d_in, const int* in_sizes, int n_in,
                              void* d_out, int out_size) {
    const float* data = (const float*)d_in[0];
    const float* W1   = (const float*)d_in[1];
    const float* b1   = (const float*)d_in[2];
    const float* W2   = (const float*)d_in[3];
    const float* b2   = (const float*)d_in[4];
    const int*   sizes_raw = (const int*)d_in[5];

    float* out = (float*)d_out;
    size_t total_e = (size_t)in_sizes[0];        // total * DIM
    float* s1o = out + total_e;
    float* s2o = s1o + (size_t)NPAIRS * MM * MM;

    cudaFuncSetAttribute(cross_kernel, cudaFuncAttributeMaxDynamicSharedMemorySize, SMEM_BYTES);

    scan_kernel<<<1, 1024>>>(sizes_raw);
    cross_kernel<<<NPAIRS, NTHREADS, SMEM_BYTES>>>(data, W1, b1, W2, b2, out, s1o, s2o);
}